// round 1
// baseline (speedup 1.0000x reference)
#include <cuda_runtime.h>
#include <math.h>

#define B_   2
#define T_   2048
#define D_   1024
#define NH_  16
#define KH_  8
#define H_   128
#define G_   2
#define EPSV 1e-6f
#define LOG_THETA 13.815510557964274f   // ln(1e6)
#define SCALE 0.08838834764831845f      // 128^-0.5
#define KMASK (-3.4028234663852886e38f)

// ---------------- scratch (device globals; no allocation allowed) ------------
__device__ float g_q[B_*T_*NH_*H_];  // 33.5 MB
__device__ float g_k[B_*T_*KH_*H_];  // 16.8 MB
__device__ float g_v[B_*T_*KH_*H_];  // 16.8 MB
__device__ float g_o[B_*T_*NH_*H_];  // 33.5 MB
__device__ int   g_pos[B_*T_];

// ---------------- positions from segment ids --------------------------------
__global__ void pos_kernel(const int* __restrict__ seg, int* __restrict__ pos) {
    int b = blockIdx.x;
    const int* s = seg + b * T_;
    __shared__ int red[256];
    int tid = threadIdx.x;
    int lm = INT_MIN;
    for (int t = tid; t < T_; t += 256) lm = max(lm, s[t]);
    red[tid] = lm; __syncthreads();
    for (int o = 128; o > 0; o >>= 1) {
        if (tid < o) red[tid] = max(red[tid], red[tid + o]);
        __syncthreads();
    }
    int mx = red[0]; __syncthreads();
    int li = T_;
    for (int t = tid; t < T_; t += 256) { if (s[t] == mx) { li = t; break; } }
    red[tid] = li; __syncthreads();
    for (int o = 128; o > 0; o >>= 1) {
        if (tid < o) red[tid] = min(red[tid], red[tid + o]);
        __syncthreads();
    }
    int off = red[0];
    for (int t = tid; t < T_; t += 256)
        pos[b * T_ + t] = (s[t] != 0) ? (t - off) : (1 << 30);
}

// ---------------- generic SGEMM: C[M,Nc] = A[M,Kd] * B[Kd,Nc] (row-major) ----
// BM=BN=128, BK=16, 256 threads, 8x8 micro-tile. All dims divisible.
__global__ void __launch_bounds__(256)
sgemm_kernel(const float* __restrict__ A, const float* __restrict__ Bm,
             float* __restrict__ C, int M, int Nc, int Kd) {
    __shared__ float As[16][128];   // transposed: As[k][m]
    __shared__ float Bs[16][128];
    int tid = threadIdx.x;
    int bm = blockIdx.y * 128, bn = blockIdx.x * 128;
    int ty = tid >> 4, tx = tid & 15;
    float acc[8][8];
#pragma unroll
    for (int i = 0; i < 8; i++)
#pragma unroll
        for (int j = 0; j < 8; j++) acc[i][j] = 0.f;

    int a_r = tid >> 2;         // 0..63
    int a_c = (tid & 3) << 2;   // 0,4,8,12
    int b_r = tid >> 5;         // 0..7
    int b_c = (tid & 31) << 2;  // 0..124
    const float* Ap = A + (size_t)(bm + a_r) * Kd + a_c;
    const float* Aq = A + (size_t)(bm + a_r + 64) * Kd + a_c;
    const float* Bp = Bm + (size_t)b_r * Nc + bn + b_c;
    const float* Bq = Bm + (size_t)(b_r + 8) * Nc + bn + b_c;

    for (int kt = 0; kt < Kd; kt += 16) {
        float4 av0 = *(const float4*)(Ap + kt);
        float4 av1 = *(const float4*)(Aq + kt);
        float4 bv0 = *(const float4*)(Bp + (size_t)kt * Nc);
        float4 bv1 = *(const float4*)(Bq + (size_t)kt * Nc);
        As[a_c + 0][a_r] = av0.x; As[a_c + 1][a_r] = av0.y;
        As[a_c + 2][a_r] = av0.z; As[a_c + 3][a_r] = av0.w;
        As[a_c + 0][a_r + 64] = av1.x; As[a_c + 1][a_r + 64] = av1.y;
        As[a_c + 2][a_r + 64] = av1.z; As[a_c + 3][a_r + 64] = av1.w;
        *(float4*)&Bs[b_r][b_c] = bv0;
        *(float4*)&Bs[b_r + 8][b_c] = bv1;
        __syncthreads();
#pragma unroll
        for (int kk = 0; kk < 16; kk++) {
            float4 a0 = *(const float4*)&As[kk][ty * 8];
            float4 a1 = *(const float4*)&As[kk][ty * 8 + 4];
            float4 b0 = *(const float4*)&Bs[kk][tx * 8];
            float4 b1 = *(const float4*)&Bs[kk][tx * 8 + 4];
            float ra[8] = {a0.x, a0.y, a0.z, a0.w, a1.x, a1.y, a1.z, a1.w};
            float rb[8] = {b0.x, b0.y, b0.z, b0.w, b1.x, b1.y, b1.z, b1.w};
#pragma unroll
            for (int i = 0; i < 8; i++)
#pragma unroll
                for (int j = 0; j < 8; j++)
                    acc[i][j] = fmaf(ra[i], rb[j], acc[i][j]);
        }
        __syncthreads();
    }
#pragma unroll
    for (int i = 0; i < 8; i++) {
        float4 c0 = make_float4(acc[i][0], acc[i][1], acc[i][2], acc[i][3]);
        float4 c1 = make_float4(acc[i][4], acc[i][5], acc[i][6], acc[i][7]);
        float* cp = C + (size_t)(bm + ty * 8 + i) * Nc + bn + tx * 8;
        *(float4*)cp = c0;
        *(float4*)(cp + 4) = c1;
    }
}

// ---------------- fused RMSNorm + RoPE (in place on g_q / g_k) ---------------
__global__ void __launch_bounds__(128)
normrope_kernel(float* __restrict__ q, float* __restrict__ k,
                const int* __restrict__ pos,
                const float* __restrict__ qscale, const float* __restrict__ kscale) {
    int gid = blockIdx.x;
    int hh = gid % (NH_ + KH_);
    int bt = gid / (NH_ + KH_);
    int h = threadIdx.x;
    float* row;
    const float* sc;
    if (hh < NH_) { row = q + ((size_t)bt * NH_ + hh) * H_;         sc = qscale; }
    else          { row = k + ((size_t)bt * KH_ + (hh - NH_)) * H_; sc = kscale; }
    float v = row[h];
    float ss = v * v;
#pragma unroll
    for (int o = 16; o > 0; o >>= 1) ss += __shfl_xor_sync(0xffffffffu, ss, o);
    __shared__ float wsum[4];
    __shared__ float rbuf[128];
    if ((h & 31) == 0) wsum[h >> 5] = ss;
    __syncthreads();
    float tot = wsum[0] + wsum[1] + wsum[2] + wsum[3];
    float rms = sqrtf(tot * (1.0f / H_) + EPSV);
    rbuf[h] = sc[h] * v / rms;
    __syncthreads();
    if (h < 64) {
        float x1 = rbuf[h], x2 = rbuf[h + 64];
        float inv_freq = expf(-((float)h * (1.0f / 64.0f)) * LOG_THETA);
        float ang = (float)pos[bt] * inv_freq;
        float s, c;
        sincosf(ang, &s, &c);
        row[h]      = x1 * c - x2 * s;
        row[h + 64] = x2 * c + x1 * s;
    }
}

// ---------------- flash-style causal GQA attention ---------------------------
// Block: one (b, q-head n, 64-query tile). 256 threads (16x16), 4x4 S tile,
// 4x8 O tile per thread. Online softmax. Dynamic smem ~116KB.
#define BQ 64
#define BS 64
#define ATTN_SMEM ((64*129 + 64*129 + 64*128 + 64*65) * 4 + 64*2*4)

__global__ void __launch_bounds__(256)
attn_kernel(const float* __restrict__ q, const float* __restrict__ k,
            const float* __restrict__ v, const int* __restrict__ pos,
            const int* __restrict__ seg, float* __restrict__ o) {
    extern __shared__ float sm[];
    float* qs = sm;                 // [64][129]
    float* ks = qs + 64 * 129;      // [64][129]
    float* vs = ks + 64 * 129;      // [64][128]
    float* ps = vs + 64 * 128;      // [64][65]
    int* poss = (int*)(ps + 64 * 65);
    int* segs = poss + 64;

    int tid = threadIdx.x;
    int qt = blockIdx.x, n = blockIdx.y, b = blockIdx.z;
    int kvh = n / G_;
    int ty = tid >> 4, tx = tid & 15;
    int r0 = ty * 4;

    const float* qg = q + (((size_t)b * T_ + qt * BQ) * NH_ + n) * H_;
    for (int idx = tid; idx < BQ * H_; idx += 256) {
        int r = idx >> 7, h = idx & 127;
        qs[r * 129 + h] = qg[(size_t)r * NH_ * H_ + h] * SCALE;
    }
    int post[4], segt[4];
#pragma unroll
    for (int i = 0; i < 4; i++) {
        int t = qt * BQ + r0 + i;
        post[i] = pos[b * T_ + t];
        segt[i] = seg[b * T_ + t];
    }
    float m[4], l[4], acc[4][8];
#pragma unroll
    for (int i = 0; i < 4; i++) {
        m[i] = KMASK; l[i] = 0.f;
#pragma unroll
        for (int j = 0; j < 8; j++) acc[i][j] = 0.f;
    }

    int nst = qt + 1;  // causal by index (pos monotone for valid tokens)
    for (int st = 0; st < nst; st++) {
        __syncthreads();  // prior PV reads of vs/ps done
        const float* kg = k + (((size_t)b * T_ + st * BS) * KH_ + kvh) * H_;
        const float* vg = v + (((size_t)b * T_ + st * BS) * KH_ + kvh) * H_;
        for (int idx = tid; idx < BS * H_; idx += 256) {
            int r = idx >> 7, h = idx & 127;
            ks[r * 129 + h] = kg[(size_t)r * KH_ * H_ + h];
            vs[r * 128 + h] = vg[(size_t)r * KH_ * H_ + h];
        }
        if (tid < BS) {
            int s = st * BS + tid;
            poss[tid] = pos[b * T_ + s];
            segs[tid] = seg[b * T_ + s];
        }
        __syncthreads();

        // S = Q K^T (4x4 per thread)
        float s4[4][4];
#pragma unroll
        for (int i = 0; i < 4; i++)
#pragma unroll
            for (int j = 0; j < 4; j++) s4[i][j] = 0.f;
#pragma unroll 4
        for (int h = 0; h < H_; h++) {
            float a0 = qs[(r0 + 0) * 129 + h];
            float a1 = qs[(r0 + 1) * 129 + h];
            float a2 = qs[(r0 + 2) * 129 + h];
            float a3 = qs[(r0 + 3) * 129 + h];
            float b0 = ks[(tx * 4 + 0) * 129 + h];
            float b1 = ks[(tx * 4 + 1) * 129 + h];
            float b2 = ks[(tx * 4 + 2) * 129 + h];
            float b3 = ks[(tx * 4 + 3) * 129 + h];
            s4[0][0] = fmaf(a0, b0, s4[0][0]); s4[0][1] = fmaf(a0, b1, s4[0][1]);
            s4[0][2] = fmaf(a0, b2, s4[0][2]); s4[0][3] = fmaf(a0, b3, s4[0][3]);
            s4[1][0] = fmaf(a1, b0, s4[1][0]); s4[1][1] = fmaf(a1, b1, s4[1][1]);
            s4[1][2] = fmaf(a1, b2, s4[1][2]); s4[1][3] = fmaf(a1, b3, s4[1][3]);
            s4[2][0] = fmaf(a2, b0, s4[2][0]); s4[2][1] = fmaf(a2, b1, s4[2][1]);
            s4[2][2] = fmaf(a2, b2, s4[2][2]); s4[2][3] = fmaf(a2, b3, s4[2][3]);
            s4[3][0] = fmaf(a3, b0, s4[3][0]); s4[3][1] = fmaf(a3, b1, s4[3][1]);
            s4[3][2] = fmaf(a3, b2, s4[3][2]); s4[3][3] = fmaf(a3, b3, s4[3][3]);
        }

        // mask + online softmax per row
#pragma unroll
        for (int i = 0; i < 4; i++) {
            float tm = KMASK;
#pragma unroll
            for (int j = 0; j < 4; j++) {
                int c = tx * 4 + j;
                bool ok = (poss[c] <= post[i]) && (segs[c] == segt[i]);
                if (!ok) s4[i][j] = KMASK;
                tm = fmaxf(tm, s4[i][j]);
            }
#pragma unroll
            for (int ofs = 8; ofs > 0; ofs >>= 1)
                tm = fmaxf(tm, __shfl_xor_sync(0xffffffffu, tm, ofs));
            float mn = fmaxf(m[i], tm);
            float alpha = expf(m[i] - mn);
            float rs = 0.f;
#pragma unroll
            for (int j = 0; j < 4; j++) {
                int c = tx * 4 + j;
                bool ok = (poss[c] <= post[i]) && (segs[c] == segt[i]);
                float p = ok ? expf(s4[i][j] - mn) : 0.f;
                ps[(r0 + i) * 65 + c] = p;
                rs += p;
            }
#pragma unroll
            for (int ofs = 8; ofs > 0; ofs >>= 1)
                rs += __shfl_xor_sync(0xffffffffu, rs, ofs);
            l[i] = l[i] * alpha + rs;
            m[i] = mn;
#pragma unroll
            for (int j = 0; j < 8; j++) acc[i][j] *= alpha;
        }
        __syncwarp();  // row group (16 tx threads) is within one warp

        // O += P V  (4x8 per thread)
#pragma unroll 2
        for (int kk = 0; kk < BS; kk++) {
            float p0 = ps[(r0 + 0) * 65 + kk];
            float p1 = ps[(r0 + 1) * 65 + kk];
            float p2 = ps[(r0 + 2) * 65 + kk];
            float p3 = ps[(r0 + 3) * 65 + kk];
            float4 v0 = *(const float4*)&vs[kk * 128 + tx * 8];
            float4 v1 = *(const float4*)&vs[kk * 128 + tx * 8 + 4];
            float vv[8] = {v0.x, v0.y, v0.z, v0.w, v1.x, v1.y, v1.z, v1.w};
#pragma unroll
            for (int j = 0; j < 8; j++) {
                acc[0][j] = fmaf(p0, vv[j], acc[0][j]);
                acc[1][j] = fmaf(p1, vv[j], acc[1][j]);
                acc[2][j] = fmaf(p2, vv[j], acc[2][j]);
                acc[3][j] = fmaf(p3, vv[j], acc[3][j]);
            }
        }
    }

#pragma unroll
    for (int i = 0; i < 4; i++) {
        float li = l[i];
        if (li <= 0.f) li = 1.f;
        float inv = 1.0f / li;
        float4 c0 = make_float4(acc[i][0] * inv, acc[i][1] * inv, acc[i][2] * inv, acc[i][3] * inv);
        float4 c1 = make_float4(acc[i][4] * inv, acc[i][5] * inv, acc[i][6] * inv, acc[i][7] * inv);
        float* op = o + (((size_t)b * T_ + qt * BQ + r0 + i) * NH_ + n) * H_ + tx * 8;
        *(float4*)op = c0;
        *(float4*)(op + 4) = c1;
    }
}

// ---------------- launch ------------------------------------------------------
extern "C" void kernel_launch(void* const* d_in, const int* in_sizes, int n_in,
                              void* d_out, int out_size) {
    const float* x   = (const float*)d_in[0];
    const int*   seg = (const int*)  d_in[1];
    const float* wq  = (const float*)d_in[2];
    const float* wk  = (const float*)d_in[3];
    const float* wv  = (const float*)d_in[4];
    const float* wo  = (const float*)d_in[5];
    const float* qsc = (const float*)d_in[6];
    const float* ksc = (const float*)d_in[7];
    float* out = (float*)d_out;

    float *q, *k, *v, *o;
    int* pos;
    cudaGetSymbolAddress((void**)&q,  g_q);
    cudaGetSymbolAddress((void**)&k,  g_k);
    cudaGetSymbolAddress((void**)&v,  g_v);
    cudaGetSymbolAddress((void**)&o,  g_o);
    cudaGetSymbolAddress((void**)&pos, g_pos);

    const int M = B_ * T_;  // 4096

    pos_kernel<<<B_, 256>>>(seg, pos);

    sgemm_kernel<<<dim3((NH_*H_)/128, M/128), 256>>>(x, wq, q, M, NH_*H_, D_);
    sgemm_kernel<<<dim3((KH_*H_)/128, M/128), 256>>>(x, wk, k, M, KH_*H_, D_);
    sgemm_kernel<<<dim3((KH_*H_)/128, M/128), 256>>>(x, wv, v, M, KH_*H_, D_);

    normrope_kernel<<<M * (NH_ + KH_), 128>>>(q, k, pos, qsc, ksc);

    cudaFuncSetAttribute(attn_kernel, cudaFuncAttributeMaxDynamicSharedMemorySize, ATTN_SMEM);
    attn_kernel<<<dim3(T_/BQ, NH_, B_), 256, ATTN_SMEM>>>(q, k, v, pos, seg, o);

    sgemm_kernel<<<dim3(D_/128, M/128), 256>>>(o, wo, out, M, D_, NH_*H_);
}

// round 13
// speedup vs baseline: 1.1663x; 1.1663x over previous
#include <stdint.h>
#include <cuda_runtime.h>
#include <cuda_bf16.h>
#include <mma.h>
#include <math.h>

using namespace nvcuda;

typedef unsigned int       u32;
typedef unsigned long long u64;

#define B_   2
#define T_   2048
#define D_   1024
#define NH_  16
#define KH_  8
#define H_   128
#define G_   2
#define EPSV 1e-6f
#define LOG_THETA 13.815510557964274f
#define SCALE 0.08838834764831845f
#define KMASK (-3.4028234663852886e38f)

#define M_ (B_*T_)   // 4096

// ---------------- scratch ----------------------------------------------------
__device__ float g_q[M_*NH_*H_];
__device__ float g_k[M_*KH_*H_];
__device__ float g_v[M_*KH_*H_];
__device__ float g_o[M_*NH_*H_];
__device__ int   g_pos[B_*T_];
// bf16 splits
__device__ __nv_bfloat16 g_x_hi[M_*D_],      g_x_lo[M_*D_];
__device__ __nv_bfloat16 g_o_hi[M_*NH_*H_],  g_o_lo[M_*NH_*H_];
__device__ __nv_bfloat16 g_wqt_hi[NH_*H_*D_],g_wqt_lo[NH_*H_*D_];
__device__ __nv_bfloat16 g_wkt_hi[KH_*H_*D_],g_wkt_lo[KH_*H_*D_];
__device__ __nv_bfloat16 g_wvt_hi[KH_*H_*D_],g_wvt_lo[KH_*H_*D_];
__device__ __nv_bfloat16 g_wot_hi[D_*NH_*H_],g_wot_lo[D_*NH_*H_];

// ---------------- positions --------------------------------------------------
__global__ void pos_kernel(const int* __restrict__ seg, int* __restrict__ pos) {
    int b = blockIdx.x;
    const int* s = seg + b * T_;
    __shared__ int red[256];
    int tid = threadIdx.x;
    int lm = -2147483647 - 1;
    for (int t = tid; t < T_; t += 256) lm = max(lm, s[t]);
    red[tid] = lm; __syncthreads();
    for (int o = 128; o > 0; o >>= 1) { if (tid < o) red[tid] = max(red[tid], red[tid+o]); __syncthreads(); }
    int mx = red[0]; __syncthreads();
    int li = T_;
    for (int t = tid; t < T_; t += 256) { if (s[t] == mx) { li = t; break; } }
    red[tid] = li; __syncthreads();
    for (int o = 128; o > 0; o >>= 1) { if (tid < o) red[tid] = min(red[tid], red[tid+o]); __syncthreads(); }
    int off = red[0];
    for (int t = tid; t < T_; t += 256)
        pos[b * T_ + t] = (s[t] != 0) ? (t - off) : (1 << 30);
}

// ---------------- fp32 -> (hi, lo) bf16 split --------------------------------
__device__ __forceinline__ u32 pack_bf16(__nv_bfloat16 a, __nv_bfloat16 b) {
    return ((u32)__bfloat16_as_ushort(b) << 16) | (u32)__bfloat16_as_ushort(a);
}
__global__ void __launch_bounds__(256)
split_kernel(const float* __restrict__ in, __nv_bfloat16* __restrict__ hi,
             __nv_bfloat16* __restrict__ lo, int n) {
    int i = (blockIdx.x * 256 + threadIdx.x) * 4;
    if (i >= n) return;
    float4 x = *(const float4*)(in + i);
    __nv_bfloat16 h0 = __float2bfloat16(x.x), h1 = __float2bfloat16(x.y);
    __nv_bfloat16 h2 = __float2bfloat16(x.z), h3 = __float2bfloat16(x.w);
    __nv_bfloat16 l0 = __float2bfloat16(x.x - __bfloat162float(h0));
    __nv_bfloat16 l1 = __float2bfloat16(x.y - __bfloat162float(h1));
    __nv_bfloat16 l2 = __float2bfloat16(x.z - __bfloat162float(h2));
    __nv_bfloat16 l3 = __float2bfloat16(x.w - __bfloat162float(h3));
    u32* hp = (u32*)(hi + i);
    u32* lp = (u32*)(lo + i);
    hp[0] = pack_bf16(h0, h1); hp[1] = pack_bf16(h2, h3);
    lp[0] = pack_bf16(l0, l1); lp[1] = pack_bf16(l2, l3);
}

// transpose + split: W[Kd][Nc] fp32 -> out[Nc][Kd] bf16 hi/lo
__global__ void __launch_bounds__(256)
tsplit_kernel(const float* __restrict__ W, __nv_bfloat16* __restrict__ hi,
              __nv_bfloat16* __restrict__ lo, int Kd, int Nc) {
    __shared__ float tile[32][33];
    int kx = blockIdx.x * 32, nx = blockIdx.y * 32;
    int tx = threadIdx.x, ty = threadIdx.y;  // 32 x 8
#pragma unroll
    for (int r = 0; r < 32; r += 8)
        tile[ty + r][tx] = W[(size_t)(kx + ty + r) * Nc + nx + tx];
    __syncthreads();
#pragma unroll
    for (int r = 0; r < 32; r += 8) {
        float x = tile[tx][ty + r];
        __nv_bfloat16 h = __float2bfloat16(x);
        __nv_bfloat16 l = __float2bfloat16(x - __bfloat162float(h));
        size_t oi = (size_t)(nx + ty + r) * Kd + kx + tx;
        hi[oi] = h; lo[oi] = l;
    }
}

// ---------------- WMMA bf16 GEMM (3-term split) -------------------------------
// C[M,Nc] = A[M,Kd] * B[Kd,Nc]. A given as hi/lo splits [M][Kd] row-major;
// B given as B^T hi/lo splits [Nc][Kd] row-major (= [Kd][Nc] col-major).
// Block tile 128x128, K-chunk 32. 8 warps in 2(M) x 4(N); warp tile 64x32.
#define LDT 40   // 32 + 8 pad (80B rows: 16B-aligned, conflict-reducing)

__global__ void __launch_bounds__(256)
wgemm_kernel(const __nv_bfloat16* __restrict__ Ah, const __nv_bfloat16* __restrict__ Al,
             const __nv_bfloat16* __restrict__ Bh, const __nv_bfloat16* __restrict__ Bl,
             float* __restrict__ C, int M, int Nc, int Kd) {
    __shared__ __nv_bfloat16 sAh[128 * LDT];
    __shared__ __nv_bfloat16 sAl[128 * LDT];
    __shared__ __nv_bfloat16 sBh[128 * LDT];
    __shared__ __nv_bfloat16 sBl[128 * LDT];

    int tid = threadIdx.x;
    int wid = tid >> 5;
    int wm = wid >> 2;        // 0..1 : 64-row band
    int wn = wid & 3;         // 0..3 : 32-col band
    int bm = blockIdx.y * 128, bn = blockIdx.x * 128;

    int row = tid >> 1;            // 0..127
    int half = (tid & 1) * 16;     // 0 or 16 (elements)

    const __nv_bfloat16* pAh = Ah + (size_t)(bm + row) * Kd + half;
    const __nv_bfloat16* pAl = Al + (size_t)(bm + row) * Kd + half;
    const __nv_bfloat16* pBh = Bh + (size_t)(bn + row) * Kd + half;
    const __nv_bfloat16* pBl = Bl + (size_t)(bn + row) * Kd + half;
    __nv_bfloat16* qAh = sAh + row * LDT + half;
    __nv_bfloat16* qAl = sAl + row * LDT + half;
    __nv_bfloat16* qBh = sBh + row * LDT + half;
    __nv_bfloat16* qBl = sBl + row * LDT + half;

    wmma::fragment<wmma::accumulator, 16, 16, 16, float> acc[4][2];
#pragma unroll
    for (int i = 0; i < 4; i++)
#pragma unroll
        for (int j = 0; j < 2; j++)
            wmma::fill_fragment(acc[i][j], 0.0f);

    for (int k0 = 0; k0 < Kd; k0 += 32) {
        // stage tiles (each thread: 8 x 16B vectors)
        *(uint4*)(qAh)     = *(const uint4*)(pAh + k0);
        *(uint4*)(qAh + 8) = *(const uint4*)(pAh + k0 + 8);
        *(uint4*)(qAl)     = *(const uint4*)(pAl + k0);
        *(uint4*)(qAl + 8) = *(const uint4*)(pAl + k0 + 8);
        *(uint4*)(qBh)     = *(const uint4*)(pBh + k0);
        *(uint4*)(qBh + 8) = *(const uint4*)(pBh + k0 + 8);
        *(uint4*)(qBl)     = *(const uint4*)(pBl + k0);
        *(uint4*)(qBl + 8) = *(const uint4*)(pBl + k0 + 8);
        __syncthreads();

#pragma unroll
        for (int kk = 0; kk < 32; kk += 16) {
            wmma::fragment<wmma::matrix_b, 16, 16, 16, __nv_bfloat16, wmma::col_major> fbh[2], fbl[2];
#pragma unroll
            for (int j = 0; j < 2; j++) {
                const __nv_bfloat16* bp = sBh + (wn * 32 + j * 16) * LDT + kk;
                const __nv_bfloat16* lp = sBl + (wn * 32 + j * 16) * LDT + kk;
                wmma::load_matrix_sync(fbh[j], bp, LDT);
                wmma::load_matrix_sync(fbl[j], lp, LDT);
            }
#pragma unroll
            for (int i = 0; i < 4; i++) {
                wmma::fragment<wmma::matrix_a, 16, 16, 16, __nv_bfloat16, wmma::row_major> fah, fal;
                wmma::load_matrix_sync(fah, sAh + (wm * 64 + i * 16) * LDT + kk, LDT);
                wmma::load_matrix_sync(fal, sAl + (wm * 64 + i * 16) * LDT + kk, LDT);
#pragma unroll
                for (int j = 0; j < 2; j++) {
                    wmma::mma_sync(acc[i][j], fah, fbh[j], acc[i][j]);
                    wmma::mma_sync(acc[i][j], fah, fbl[j], acc[i][j]);
                    wmma::mma_sync(acc[i][j], fal, fbh[j], acc[i][j]);
                }
            }
        }
        __syncthreads();
    }

#pragma unroll
    for (int i = 0; i < 4; i++)
#pragma unroll
        for (int j = 0; j < 2; j++)
            wmma::store_matrix_sync(
                C + (size_t)(bm + wm * 64 + i * 16) * Nc + bn + wn * 32 + j * 16,
                acc[i][j], Nc, wmma::mem_row_major);
}

// ---------------- fused RMSNorm + RoPE ---------------------------------------
__global__ void __launch_bounds__(128)
normrope_kernel(float* __restrict__ q, float* __restrict__ k,
                const int* __restrict__ pos,
                const float* __restrict__ qscale, const float* __restrict__ kscale) {
    int gid = blockIdx.x;
    int hh = gid % (NH_ + KH_);
    int bt = gid / (NH_ + KH_);
    int h = threadIdx.x;
    float* row;
    const float* sc;
    if (hh < NH_) { row = q + ((size_t)bt * NH_ + hh) * H_;         sc = qscale; }
    else          { row = k + ((size_t)bt * KH_ + (hh - NH_)) * H_; sc = kscale; }
    float v = row[h];
    float ss = v * v;
#pragma unroll
    for (int o = 16; o > 0; o >>= 1) ss += __shfl_xor_sync(0xffffffffu, ss, o);
    __shared__ float wsum[4];
    __shared__ float rbuf[128];
    if ((h & 31) == 0) wsum[h >> 5] = ss;
    __syncthreads();
    float tot = wsum[0] + wsum[1] + wsum[2] + wsum[3];
    float rms = sqrtf(tot * (1.0f / H_) + EPSV);
    rbuf[h] = sc[h] * v / rms;
    __syncthreads();
    if (h < 64) {
        float x1 = rbuf[h], x2 = rbuf[h + 64];
        float inv_freq = expf(-((float)h * (1.0f / 64.0f)) * LOG_THETA);
        float ang = (float)pos[bt] * inv_freq;
        float s, c;
        sincosf(ang, &s, &c);
        row[h]      = x1 * c - x2 * s;
        row[h + 64] = x2 * c + x1 * s;
    }
}

// ---------------- flash-style causal GQA attention (SIMT, fp32) --------------
#define BQ 64
#define BS 64
#define ATTN_SMEM ((64*129 + 64*129 + 64*128 + 64*65) * 4 + 64*2*4)

__global__ void __launch_bounds__(256)
attn_kernel(const float* __restrict__ q, const float* __restrict__ k,
            const float* __restrict__ v, const int* __restrict__ pos,
            const int* __restrict__ seg, float* __restrict__ o) {
    extern __shared__ float sm[];
    float* qs = sm;
    float* ks = qs + 64 * 129;
    float* vs = ks + 64 * 129;
    float* ps = vs + 64 * 128;
    int* poss = (int*)(ps + 64 * 65);
    int* segs = poss + 64;

    int tid = threadIdx.x;
    int qt = blockIdx.x, n = blockIdx.y, b = blockIdx.z;
    int kvh = n / G_;
    int ty = tid >> 4, tx = tid & 15;
    int r0 = ty * 4;

    const float* qg = q + (((size_t)b * T_ + qt * BQ) * NH_ + n) * H_;
    for (int idx = tid; idx < BQ * H_; idx += 256) {
        int r = idx >> 7, h = idx & 127;
        qs[r * 129 + h] = qg[(size_t)r * NH_ * H_ + h] * SCALE;
    }
    int post[4], segt[4];
#pragma unroll
    for (int i = 0; i < 4; i++) {
        int t = qt * BQ + r0 + i;
        post[i] = pos[b * T_ + t];
        segt[i] = seg[b * T_ + t];
    }
    float m[4], l[4], acc[4][8];
#pragma unroll
    for (int i = 0; i < 4; i++) {
        m[i] = KMASK; l[i] = 0.f;
#pragma unroll
        for (int j = 0; j < 8; j++) acc[i][j] = 0.f;
    }

    int nst = qt + 1;
    for (int st = 0; st < nst; st++) {
        __syncthreads();
        const float* kg = k + (((size_t)b * T_ + st * BS) * KH_ + kvh) * H_;
        const float* vg = v + (((size_t)b * T_ + st * BS) * KH_ + kvh) * H_;
        for (int idx = tid; idx < BS * H_; idx += 256) {
            int r = idx >> 7, h = idx & 127;
            ks[r * 129 + h] = kg[(size_t)r * KH_ * H_ + h];
            vs[r * 128 + h] = vg[(size_t)r * KH_ * H_ + h];
        }
        if (tid < BS) {
            int s = st * BS + tid;
            poss[tid] = pos[b * T_ + s];
            segs[tid] = seg[b * T_ + s];
        }
        __syncthreads();

        float s4[4][4];
#pragma unroll
        for (int i = 0; i < 4; i++)
#pragma unroll
            for (int j = 0; j < 4; j++) s4[i][j] = 0.f;
#pragma unroll 4
        for (int h = 0; h < H_; h++) {
            float a0 = qs[(r0 + 0) * 129 + h];
            float a1 = qs[(r0 + 1) * 129 + h];
            float a2 = qs[(r0 + 2) * 129 + h];
            float a3 = qs[(r0 + 3) * 129 + h];
            float b0 = ks[(tx * 4 + 0) * 129 + h];
            float b1 = ks[(tx * 4 + 1) * 129 + h];
            float b2 = ks[(tx * 4 + 2) * 129 + h];
            float b3 = ks[(tx * 4 + 3) * 129 + h];
            s4[0][0] = fmaf(a0, b0, s4[0][0]); s4[0][1] = fmaf(a0, b1, s4[0][1]);
            s4[0][2] = fmaf(a0, b2, s4[0][2]); s4[0][3] = fmaf(a0, b3, s4[0][3]);
            s4[1][0] = fmaf(a1, b0, s4[1][0]); s4[1][1] = fmaf(a1, b1, s4[1][1]);
            s4[1][2] = fmaf(a1, b2, s4[1][2]); s4[1][3] = fmaf(a1, b3, s4[1][3]);
            s4[2][0] = fmaf(a2, b0, s4[2][0]); s4[2][1] = fmaf(a2, b1, s4[2][1]);
            s4[2][2] = fmaf(a2, b2, s4[2][2]); s4[2][3] = fmaf(a2, b3, s4[2][3]);
            s4[3][0] = fmaf(a3, b0, s4[3][0]); s4[3][1] = fmaf(a3, b1, s4[3][1]);
            s4[3][2] = fmaf(a3, b2, s4[3][2]); s4[3][3] = fmaf(a3, b3, s4[3][3]);
        }

#pragma unroll
        for (int i = 0; i < 4; i++) {
            float tm = KMASK;
#pragma unroll
            for (int j = 0; j < 4; j++) {
                int c = tx * 4 + j;
                bool ok = (poss[c] <= post[i]) && (segs[c] == segt[i]);
                if (!ok) s4[i][j] = KMASK;
                tm = fmaxf(tm, s4[i][j]);
            }
#pragma unroll
            for (int ofs = 8; ofs > 0; ofs >>= 1)
                tm = fmaxf(tm, __shfl_xor_sync(0xffffffffu, tm, ofs));
            float mn = fmaxf(m[i], tm);
            float alpha = expf(m[i] - mn);
            float rs = 0.f;
#pragma unroll
            for (int j = 0; j < 4; j++) {
                int c = tx * 4 + j;
                bool ok = (poss[c] <= post[i]) && (segs[c] == segt[i]);
                float p = ok ? expf(s4[i][j] - mn) : 0.f;
                ps[(r0 + i) * 65 + c] = p;
                rs += p;
            }
#pragma unroll
            for (int ofs = 8; ofs > 0; ofs >>= 1)
                rs += __shfl_xor_sync(0xffffffffu, rs, ofs);
            l[i] = l[i] * alpha + rs;
            m[i] = mn;
#pragma unroll
            for (int j = 0; j < 8; j++) acc[i][j] *= alpha;
        }
        __syncwarp();

#pragma unroll 2
        for (int kk = 0; kk < BS; kk++) {
            float p0 = ps[(r0 + 0) * 65 + kk];
            float p1 = ps[(r0 + 1) * 65 + kk];
            float p2 = ps[(r0 + 2) * 65 + kk];
            float p3 = ps[(r0 + 3) * 65 + kk];
            float4 v0 = *(const float4*)&vs[kk * 128 + tx * 8];
            float4 v1 = *(const float4*)&vs[kk * 128 + tx * 8 + 4];
            float vv[8] = {v0.x, v0.y, v0.z, v0.w, v1.x, v1.y, v1.z, v1.w};
#pragma unroll
            for (int j = 0; j < 8; j++) {
                acc[0][j] = fmaf(p0, vv[j], acc[0][j]);
                acc[1][j] = fmaf(p1, vv[j], acc[1][j]);
                acc[2][j] = fmaf(p2, vv[j], acc[2][j]);
                acc[3][j] = fmaf(p3, vv[j], acc[3][j]);
            }
        }
    }

#pragma unroll
    for (int i = 0; i < 4; i++) {
        float li = l[i];
        if (li <= 0.f) li = 1.f;
        float inv = 1.0f / li;
        float4 c0 = make_float4(acc[i][0]*inv, acc[i][1]*inv, acc[i][2]*inv, acc[i][3]*inv);
        float4 c1 = make_float4(acc[i][4]*inv, acc[i][5]*inv, acc[i][6]*inv, acc[i][7]*inv);
        float* op = o + (((size_t)b * T_ + qt * BQ + r0 + i) * NH_ + n) * H_ + tx * 8;
        *(float4*)op = c0;
        *(float4*)(op + 4) = c1;
    }
}

// ---------------- launch ------------------------------------------------------
extern "C" void kernel_launch(void* const* d_in, const int* in_sizes, int n_in,
                              void* d_out, int out_size) {
    const float* x   = (const float*)d_in[0];
    const int*   seg = (const int*)  d_in[1];
    const float* wq  = (const float*)d_in[2];
    const float* wk  = (const float*)d_in[3];
    const float* wv  = (const float*)d_in[4];
    const float* wo  = (const float*)d_in[5];
    const float* qsc = (const float*)d_in[6];
    const float* ksc = (const float*)d_in[7];
    float* out = (float*)d_out;

    float *q, *k, *v, *o;
    int* pos;
    __nv_bfloat16 *xh, *xl, *oh, *ol, *wqh, *wql, *wkh, *wkl, *wvh, *wvl, *woh, *wol;
    cudaGetSymbolAddress((void**)&q,   g_q);
    cudaGetSymbolAddress((void**)&k,   g_k);
    cudaGetSymbolAddress((void**)&v,   g_v);
    cudaGetSymbolAddress((void**)&o,   g_o);
    cudaGetSymbolAddress((void**)&pos, g_pos);
    cudaGetSymbolAddress((void**)&xh,  g_x_hi);  cudaGetSymbolAddress((void**)&xl,  g_x_lo);
    cudaGetSymbolAddress((void**)&oh,  g_o_hi);  cudaGetSymbolAddress((void**)&ol,  g_o_lo);
    cudaGetSymbolAddress((void**)&wqh, g_wqt_hi); cudaGetSymbolAddress((void**)&wql, g_wqt_lo);
    cudaGetSymbolAddress((void**)&wkh, g_wkt_hi); cudaGetSymbolAddress((void**)&wkl, g_wkt_lo);
    cudaGetSymbolAddress((void**)&wvh, g_wvt_hi); cudaGetSymbolAddress((void**)&wvl, g_wvt_lo);
    cudaGetSymbolAddress((void**)&woh, g_wot_hi); cudaGetSymbolAddress((void**)&wol, g_wot_lo);

    cudaFuncSetAttribute(attn_kernel, cudaFuncAttributeMaxDynamicSharedMemorySize, ATTN_SMEM);

    pos_kernel<<<B_, 256>>>(seg, pos);

    // splits / transposes
    split_kernel<<<(M_*D_/4 + 255)/256, 256>>>(x, xh, xl, M_*D_);
    dim3 tb(32, 8);
    tsplit_kernel<<<dim3(D_/32, (NH_*H_)/32), tb>>>(wq, wqh, wql, D_, NH_*H_);
    tsplit_kernel<<<dim3(D_/32, (KH_*H_)/32), tb>>>(wk, wkh, wkl, D_, KH_*H_);
    tsplit_kernel<<<dim3(D_/32, (KH_*H_)/32), tb>>>(wv, wvh, wvl, D_, KH_*H_);
    tsplit_kernel<<<dim3((NH_*H_)/32, D_/32), tb>>>(wo, woh, wol, NH_*H_, D_);

    // projections on tensor cores (WMMA/HMMA)
    wgemm_kernel<<<dim3((NH_*H_)/128, M_/128), 256>>>(xh, xl, wqh, wql, q, M_, NH_*H_, D_);
    wgemm_kernel<<<dim3((KH_*H_)/128, M_/128), 256>>>(xh, xl, wkh, wkl, k, M_, KH_*H_, D_);
    wgemm_kernel<<<dim3((KH_*H_)/128, M_/128), 256>>>(xh, xl, wvh, wvl, v, M_, KH_*H_, D_);

    normrope_kernel<<<M_ * (NH_ + KH_), 128>>>(q, k, pos, qsc, ksc);

    attn_kernel<<<dim3(T_/BQ, NH_, B_), 256, ATTN_SMEM>>>(q, k, v, pos, seg, o);

    split_kernel<<<(M_*NH_*H_/4 + 255)/256, 256>>>(o, oh, ol, M_*NH_*H_);
    wgemm_kernel<<<dim3(D_/128, M_/128), 256>>>(oh, ol, woh, wol, out, M_, D_, NH_*H_);
}